// round 11
// baseline (speedup 1.0000x reference)
#include <cuda_runtime.h>

#define EPS 1e-8f
typedef unsigned long long ull;

constexpr int RS2 = 580;                 // img half row stride (floats)
// img addr: r*RS2 + 4*(r/6) + kh + 4*(kh/32), kh in [0,512)
constexpr int OFF_CH  = 20896;           // chunk buffer / ATT overlay region (6336 floats)
constexpr int CC      = 1448;            // chunk per-cap stride
constexpr int ATT_CI  = 1584;            // ATT per-cap stride (36 rows * 44)
constexpr int OFF_W1  = OFF_CH + 6336;   // 27232
constexpr int OFF_B1v = OFF_W1 + 256;
constexpr int OFF_W2S = OFF_B1v + 8;
constexpr int OFF_B2S = OFF_W2S + 8;
constexpr int OFF_RED = OFF_B2S + 4;
constexpr int SMEM_FLOATS = OFF_RED + 160;      // 27668
constexpr int SMEM_BYTES  = SMEM_FLOATS * 4;    // 110,672 B -> 2 CTAs/SM

__device__ float g_cos[1024 * 5120];     // per-CTA cosine scratch (block-local use)

__device__ __forceinline__ ull dup2(float a) {
    ull r; asm("mov.b64 %0, {%1, %1};" : "=l"(r) : "f"(a)); return r;
}
__device__ __forceinline__ void f2(ull& d, ull a, ull b) {
    asm("fma.rn.f32x2 %0, %1, %2, %0;" : "+l"(d) : "l"(a), "l"(b));
}
__device__ __forceinline__ void up(ull v, float& lo, float& hi) {
    asm("mov.b64 {%0, %1}, %2;" : "=f"(lo), "=f"(hi) : "l"(v));
}

__global__ __launch_bounds__(256, 2)
void tg_kernel(const float* __restrict__ images, const float* __restrict__ captions,
               const int* __restrict__ cap_lens, const float* __restrict__ rare,
               const float* __restrict__ v1, const float* __restrict__ g1, const float* __restrict__ b1,
               const float* __restrict__ v2, const float* __restrict__ g2, const float* __restrict__ b2,
               const int* __restrict__ lam_p, float* __restrict__ out)
{
    extern __shared__ float sm[];
    const int tid = threadIdx.x;
    const int img = blockIdx.x;
    const int c0  = blockIdx.y * 4;
    const int bl  = blockIdx.y * 64 + blockIdx.x;

    // ---- load one image k-half into SMEM (half in {0,1}) ----
    #define LOAD_HALF(HALF) { \
        const float* gsrc = images + (size_t)img * 36864 + (HALF) * 512; \
        for (int s = 0; s < 18; s++) { \
            int idx = tid + 256 * s; \
            int r = idx >> 7, k4f = (idx & 127) * 4; \
            *(float4*)(sm + r * RS2 + 4 * (r / 6) + k4f + 4 * (k4f >> 5)) = \
                *(const float4*)(gsrc + r * 1024 + k4f); \
        } }

    // ---- weights preamble ----
    if (tid < 8) {
        int j = tid; float s = 0.f;
        for (int n = 0; n < 32; n++) { float v = v1[j * 32 + n]; s += v * v; }
        float inv = g1[j] / sqrtf(s);
        for (int n = 0; n < 32; n++) sm[OFF_W1 + j * 32 + n] = v1[j * 32 + n] * inv;
        sm[OFF_B1v + j] = b1[j];
    }
    if (tid == 8) {
        float w2s[8] = {0,0,0,0,0,0,0,0}; float b2s = 0.f;
        for (int k = 0; k < 6; k++) {
            float s = 0.f;
            for (int j = 0; j < 8; j++) { float v = v2[k * 8 + j]; s += v * v; }
            float inv = g2[k] / sqrtf(s);
            for (int j = 0; j < 8; j++) w2s[j] += v2[k * 8 + j] * inv;
            b2s += b2[k];
        }
        for (int j = 0; j < 8; j++) sm[OFF_W2S + j] = w2s[j];
        sm[OFF_B2S] = b2s;
    }
    const float lam = (float)(*lam_p);

    // Phase A map (tid<192): lg slow, capi, rg fast
    const int lg = (tid % 192) / 24, r3 = tid % 24, capi = r3 / 6, rg = r3 % 6;
    const int mylen = cap_lens[c0 + capi];
    const bool inA  = (tid < 192);
    const bool actA = inA && (lg * 5 < mylen);
    const int lg5 = lg * 5;

    ull acc[6][5];
    #pragma unroll
    for (int q = 0; q < 6; q++)
        #pragma unroll
        for (int j = 0; j < 5; j++) acc[q][j] = 0ull;

    const float* ibase = sm + rg * (6 * RS2) + 4 * rg;
    const float* cbase = sm + OFF_CH + capi * CC + lg5 * 36;

    LOAD_HALF(1)

    // ================= Phase A: two k-half passes, acc in regs =================
    #pragma unroll 1
    for (int pass = 0; pass < 2; pass++) {
        const int h = 1 - pass;                 // pass0: half1, pass1: half0
        if (pass == 1) { __syncthreads(); LOAD_HALF(0) }
        #pragma unroll 1
        for (int kc = 0; kc < 16; kc++) {
            __syncthreads();
            {   // fill chunk [4][40][32] at k = h*512 + kc*32 (5 float4/thread)
                const int koff = h * 512 + kc * 32;
                #pragma unroll
                for (int s = 0; s < 5; s++) {
                    int idx = tid + 256 * s;
                    int ci = idx / 320, r2 = idx % 320, l = r2 >> 3, k4 = (r2 & 7) * 4;
                    *(float4*)(sm + OFF_CH + ci * CC + l * 36 + k4) =
                        *(const float4*)(captions + (((size_t)(c0 + ci) * 40 + l) << 10) + koff + k4);
                }
            }
            __syncthreads();
            if (actA) {
                const float* ib = ibase + kc * 36;
                #pragma unroll
                for (int k4 = 0; k4 < 32; k4 += 4) {
                    ulonglong2 I[6], C[5];
                    #pragma unroll
                    for (int q = 0; q < 6; q++) I[q] = *(const ulonglong2*)(ib + q * RS2 + k4);
                    #pragma unroll
                    for (int j = 0; j < 5; j++) C[j] = *(const ulonglong2*)(cbase + j * 36 + k4);
                    #pragma unroll
                    for (int q = 0; q < 6; q++)
                        #pragma unroll
                        for (int j = 0; j < 5; j++) {
                            f2(acc[q][j], I[q].x, C[j].x);
                            f2(acc[q][j], I[q].y, C[j].y);
                        }
                }
            }
        }
    }
    __syncthreads();   // chunk region now becomes ATT

    // ---- epilogue: leaky-relu + mask -> ATT (stride 44) ----
    if (inA) {
        float* base = sm + OFF_CH + capi * ATT_CI;
        #pragma unroll
        for (int q = 0; q < 6; q++)
            #pragma unroll
            for (int j = 0; j < 5; j++) {
                float lo, hi; up(acc[q][j], lo, hi);
                float v = lo + hi;
                v = (v > 0.f ? v : 0.1f * v);
                int w = lg5 + j;
                base[(rg * 6 + q) * 44 + w] = (w < mylen) ? v : 0.f;
            }
    }
    __syncthreads();

    // ===== B1: l2 norm over words per region =====
    if (tid < 144) {
        int ci = tid / 36, r = tid % 36;
        float* row = sm + OFF_CH + ci * ATT_CI + r * 44;
        float s = 0.f;
        #pragma unroll 8
        for (int l = 0; l < 40; l++) { float v = row[l]; s += v * v; }
        float inv = 1.f / (sqrtf(s) + EPS);
        #pragma unroll 8
        for (int l = 0; l < 40; l++) row[l] *= inv;
    }
    __syncthreads();

    // ===== B2: softmax over regions, IN-PLACE (column l private per thread) =====
    if (tid < 160) {
        int ci = tid / 40, l = tid % 40;
        int len = cap_lens[c0 + ci];
        float* base = sm + OFF_CH + ci * ATT_CI;
        if (l < len) {
            float e[36]; float ssum = 0.f;
            #pragma unroll
            for (int r = 0; r < 36; r++) { e[r] = __expf(base[r * 44 + l] * lam); ssum += e[r]; }
            float inv = 1.f / ssum;
            #pragma unroll
            for (int r = 0; r < 36; r++) base[r * 44 + l] = e[r] * inv;
        } else {
            #pragma unroll
            for (int r = 0; r < 36; r++) base[r * 44 + l] = 0.f;
        }
    }
    __syncthreads();

    // ===== Phase C: per-warp (ci, 4-word group); lanes = 16 nbl x 2 dim-subs =====
    {
        const int warp = tid >> 5, nb = tid & 15, sub = (tid >> 4) & 1;
        const int kh = nb * 32 + sub * 16;               // local dim offset in half
        const float* ip0 = sm + kh + 4 * nb;             // + r*580 + 4*(r/6)
        #pragma unroll 1
        for (int hp = 0; hp < 2; hp++) {                 // hp0: half0 (resident), hp1: half1
            if (hp == 1) { __syncthreads(); LOAD_HALF(1) __syncthreads(); }
            #pragma unroll 1
            for (int g = warp; g < 40; g += 8) {
                const int ci = g & 3, wg = g >> 2;
                const int w0 = wg * 4;
                const int len = cap_lens[c0 + ci];
                if (w0 >= len) continue;
                const float* a2 = sm + OFF_CH + ci * ATT_CI + w0;
                float W12[4] = {0,0,0,0}, CN[4] = {0,0,0,0}, QN[4] = {0,0,0,0};
                ull wc[4][8];
                #pragma unroll
                for (int w = 0; w < 4; w++)
                    #pragma unroll
                    for (int e = 0; e < 8; e++) wc[w][e] = 0ull;
                #pragma unroll 1
                for (int rb = 0; rb < 6; rb++) {
                    const float* ipb = ip0 + rb * (6 * RS2) + 4 * rb;
                    const float* a2b = a2 + rb * (6 * 44);
                    #pragma unroll
                    for (int q = 0; q < 6; q++) {
                        float4 av = *(const float4*)(a2b + q * 44);
                        const ulonglong2* ip = (const ulonglong2*)(ipb + q * RS2);
                        ulonglong2 v0 = ip[0], v1 = ip[1], v2 = ip[2], v3 = ip[3];
                        #define CW(W, AV) { ull d_ = dup2(AV); \
                            f2(wc[W][0], d_, v0.x); f2(wc[W][1], d_, v0.y); \
                            f2(wc[W][2], d_, v1.x); f2(wc[W][3], d_, v1.y); \
                            f2(wc[W][4], d_, v2.x); f2(wc[W][5], d_, v2.y); \
                            f2(wc[W][6], d_, v3.x); f2(wc[W][7], d_, v3.y); }
                        CW(0, av.x) CW(1, av.y) CW(2, av.z) CW(3, av.w)
                        #undef CW
                    }
                }
                const int kg = hp * 512 + kh;
                #pragma unroll
                for (int w = 0; w < 4; w++) {
                    const float* qp = captions + (((size_t)(c0 + ci) * 40 + w0 + w) << 10) + kg;
                    float4 qa = *(const float4*)qp;
                    float4 qb = *(const float4*)(qp + 4);
                    float4 qc = *(const float4*)(qp + 8);
                    float4 qd = *(const float4*)(qp + 12);
                    float lo, hi;
                    up(wc[w][0], lo, hi); W12[w] += lo * qa.x + hi * qa.y; CN[w] += lo * lo + hi * hi; QN[w] += qa.x * qa.x + qa.y * qa.y;
                    up(wc[w][1], lo, hi); W12[w] += lo * qa.z + hi * qa.w; CN[w] += lo * lo + hi * hi; QN[w] += qa.z * qa.z + qa.w * qa.w;
                    up(wc[w][2], lo, hi); W12[w] += lo * qb.x + hi * qb.y; CN[w] += lo * lo + hi * hi; QN[w] += qb.x * qb.x + qb.y * qb.y;
                    up(wc[w][3], lo, hi); W12[w] += lo * qb.z + hi * qb.w; CN[w] += lo * lo + hi * hi; QN[w] += qb.z * qb.z + qb.w * qb.w;
                    up(wc[w][4], lo, hi); W12[w] += lo * qc.x + hi * qc.y; CN[w] += lo * lo + hi * hi; QN[w] += qc.x * qc.x + qc.y * qc.y;
                    up(wc[w][5], lo, hi); W12[w] += lo * qc.z + hi * qc.w; CN[w] += lo * lo + hi * hi; QN[w] += qc.z * qc.z + qc.w * qc.w;
                    up(wc[w][6], lo, hi); W12[w] += lo * qd.x + hi * qd.y; CN[w] += lo * lo + hi * hi; QN[w] += qd.x * qd.x + qd.y * qd.y;
                    up(wc[w][7], lo, hi); W12[w] += lo * qd.z + hi * qd.w; CN[w] += lo * lo + hi * hi; QN[w] += qd.z * qd.z + qd.w * qd.w;
                }
                #pragma unroll
                for (int w = 0; w < 4; w++) {
                    W12[w] += __shfl_xor_sync(0xffffffffu, W12[w], 16);
                    CN[w]  += __shfl_xor_sync(0xffffffffu, CN[w], 16);
                    QN[w]  += __shfl_xor_sync(0xffffffffu, QN[w], 16);
                }
                if (sub == 0) {
                    #pragma unroll
                    for (int w = 0; w < 4; w++)
                        g_cos[(size_t)bl * 5120 + ci * 1280 + (w0 + w) * 32 + hp * 16 + nb] =
                            W12[w] / fmaxf(sqrtf(CN[w]) * sqrtf(QN[w]), EPS);
                }
            }
        }
    }
    __syncthreads();

    // ===== Phase D: weight-normed MLP + masked mean (cos from scratch) =====
    if (tid < 160) {
        int ci = tid / 40, l = tid % 40;
        int len = cap_lens[c0 + ci];
        float res = 0.f;
        if (l < len) {
            const float* rr = rare + ((size_t)(c0 + ci) * 40 + l) * 32;
            const float* cb = g_cos + (size_t)bl * 5120 + ci * 1280 + l * 32;
            float x[32];
            #pragma unroll
            for (int n = 0; n < 32; n++) x[n] = cb[n] + 0.4f * rr[n];
            float persum = sm[OFF_B2S];
            #pragma unroll
            for (int j = 0; j < 8; j++) {
                float hsum = sm[OFF_B1v + j];
                const float* wr = sm + OFF_W1 + j * 32;
                #pragma unroll
                for (int n = 0; n < 32; n++) hsum = fmaf(x[n], wr[n], hsum);
                float hc = fminf(fmaxf(hsum, -15.f), 15.f);
                float t = __expf(2.f * hc);
                float th = __fdividef(t - 1.f, t + 1.f);
                persum = fmaf(th, sm[OFF_W2S + j], persum);
            }
            res = persum;
        }
        sm[OFF_RED + tid] = res;
    }
    __syncthreads();
    if (tid < 4) {
        int len = cap_lens[c0 + tid];
        float s = 0.f;
        for (int l = 0; l < len; l++) s += sm[OFF_RED + tid * 40 + l];
        out[(size_t)img * 64 + (c0 + tid)] = s / (float)(len * 6);
    }
}

extern "C" void kernel_launch(void* const* d_in, const int* in_sizes, int n_in,
                              void* d_out, int out_size) {
    const float* images   = (const float*)d_in[0];
    const float* captions = (const float*)d_in[1];
    const int*   cap_lens = (const int*)d_in[2];
    const float* rare     = (const float*)d_in[3];
    const float* v1       = (const float*)d_in[4];
    const float* g1       = (const float*)d_in[5];
    const float* b1       = (const float*)d_in[6];
    const float* v2       = (const float*)d_in[7];
    const float* g2       = (const float*)d_in[8];
    const float* b2       = (const float*)d_in[9];
    const int*   lam      = (const int*)d_in[12];
    float* out = (float*)d_out;

    cudaFuncSetAttribute(tg_kernel, cudaFuncAttributeMaxDynamicSharedMemorySize, SMEM_BYTES);
    tg_kernel<<<dim3(64, 16, 1), 256, SMEM_BYTES>>>(
        images, captions, cap_lens, rare, v1, g1, b1, v2, g2, b2, lam, out);
}